// round 6
// baseline (speedup 1.0000x reference)
#include <cuda_runtime.h>
#include <cuda_fp16.h>
#include <cstdint>

#define N_NODES 100000
#define F 64
#define E_MAX 2000000
#define SCAN_BLK 1024
#define NSCAN ((N_NODES + SCAN_BLK - 1) / SCAN_BLK)   // 98

// ---- scratch (allocation-free rule: __device__ globals) ----
__device__ int     g_deg[N_NODES];
__device__ int     g_off[N_NODES + 1];
__device__ int     g_cursor[N_NODES];
__device__ int     g_bsum[128];                   // padded >= NSCAN
__device__ int2    g_es[E_MAX];                   // bucketed (col, val_bits)
__device__ __half2 g_z[N_NODES * (F / 2)];        // z = x @ W, fp16, 12.8 MB

// ---------------------------------------------------------------------------
// 1. zero degree counters
// ---------------------------------------------------------------------------
__global__ void zero_deg_kernel() {
    for (int i = blockIdx.x * blockDim.x + threadIdx.x; i < N_NODES;
         i += gridDim.x * blockDim.x)
        g_deg[i] = 0;
}

// ---------------------------------------------------------------------------
// 2. histogram of edge_row
// ---------------------------------------------------------------------------
__global__ void hist_kernel(const int* __restrict__ edge_row, int n_edges) {
    for (int e = blockIdx.x * blockDim.x + threadIdx.x; e < n_edges;
         e += gridDim.x * blockDim.x)
        atomicAdd(&g_deg[edge_row[e]], 1);
}

// ---------------------------------------------------------------------------
// 3a. per-block exclusive scan of degrees; block totals to g_bsum
// ---------------------------------------------------------------------------
__global__ void scan_local_kernel() {
    __shared__ int warp_sums[32];
    const int i    = blockIdx.x * SCAN_BLK + threadIdx.x;
    const int lane = threadIdx.x & 31;
    const int wid  = threadIdx.x >> 5;

    int v = (i < N_NODES) ? g_deg[i] : 0;
    int s = v;
#pragma unroll
    for (int o = 1; o < 32; o <<= 1) {
        int t = __shfl_up_sync(0xffffffffu, s, o);
        if (lane >= o) s += t;
    }
    if (lane == 31) warp_sums[wid] = s;
    __syncthreads();
    if (wid == 0) {
        int ws = warp_sums[lane];
#pragma unroll
        for (int o = 1; o < 32; o <<= 1) {
            int t = __shfl_up_sync(0xffffffffu, ws, o);
            if (lane >= o) ws += t;
        }
        warp_sums[lane] = ws;
    }
    __syncthreads();
    const int incl = s + (wid > 0 ? warp_sums[wid - 1] : 0);
    if (i < N_NODES) g_off[i] = incl - v;                 // block-local exclusive
    if (threadIdx.x == SCAN_BLK - 1) g_bsum[blockIdx.x] = warp_sums[31];
}

// ---------------------------------------------------------------------------
// 3b. add block prefix (computed inline from g_bsum) ; init cursors ; total
// ---------------------------------------------------------------------------
__global__ void scan_add_kernel() {
    __shared__ int s_prefix;
    const int lane = threadIdx.x & 31;

    if (threadIdx.x < 32) {
        int part = 0, full = 0;
        for (int j = lane; j < NSCAN; j += 32) {
            const int b = g_bsum[j];
            full += b;
            if (j < blockIdx.x) part += b;
        }
#pragma unroll
        for (int o = 16; o > 0; o >>= 1) {
            part += __shfl_xor_sync(0xffffffffu, part, o);
            full += __shfl_xor_sync(0xffffffffu, full, o);
        }
        if (lane == 0) {
            s_prefix = part;
            if (blockIdx.x == gridDim.x - 1) g_off[N_NODES] = full;  // == n_edges
        }
    }
    __syncthreads();

    const int i = blockIdx.x * SCAN_BLK + threadIdx.x;
    if (i < N_NODES) {
        const int o = g_off[i] + s_prefix;
        g_off[i]    = o;
        g_cursor[i] = o;
    }
}

// ---------------------------------------------------------------------------
// 4. bucket edges by row
// ---------------------------------------------------------------------------
__global__ void bucket_kernel(const int*   __restrict__ edge_row,
                              const int*   __restrict__ edge_col,
                              const float* __restrict__ edge_val,
                              int n_edges) {
    for (int e = blockIdx.x * blockDim.x + threadIdx.x; e < n_edges;
         e += gridDim.x * blockDim.x) {
        const int r = edge_row[e];
        const int p = atomicAdd(&g_cursor[r], 1);
        g_es[p] = make_int2(edge_col[e], __float_as_int(edge_val[e]));
    }
}

// ---------------------------------------------------------------------------
// 5. z = x @ W  (fp16 output). One warp per row; W in smem as float2.
// ---------------------------------------------------------------------------
__global__ void zgemm_kernel(const float* __restrict__ x,
                             const float* __restrict__ weight) {
    __shared__ float2 sW2[F * 32];        // sW2[k*32 + L] = (W[k][2L], W[k][2L+1])

    for (int i = threadIdx.x; i < F * 32; i += blockDim.x)
        sW2[i] = reinterpret_cast<const float2*>(weight)[i];
    __syncthreads();

    const int lane = threadIdx.x & 31;
    const int row  = blockIdx.x * (blockDim.x >> 5) + (threadIdx.x >> 5);
    if (row >= N_NODES) return;

    const float2 s = reinterpret_cast<const float2*>(x + (size_t)row * F)[lane];

    float acc0 = 0.f, acc1 = 0.f;
#pragma unroll
    for (int k = 0; k < 32; k++) {
        const float sk0 = __shfl_sync(0xffffffffu, s.x, k);   // x[2k]
        const float sk1 = __shfl_sync(0xffffffffu, s.y, k);   // x[2k+1]
        const float2 w0 = sW2[(2 * k) * 32 + lane];
        const float2 w1 = sW2[(2 * k + 1) * 32 + lane];
        acc0 += sk0 * w0.x + sk1 * w1.x;
        acc1 += sk0 * w0.y + sk1 * w1.y;
    }

    g_z[(size_t)row * 32 + lane] = __floats2half2_rn(acc0, acc1);
}

// ---------------------------------------------------------------------------
// 6. fused pull + bias + L2 normalize.
// Warp per row. Descriptor prefetch: lane i holds g_es[beg+i] (chunk of <=32
// edges in one coalesced LDG).  Then 4 edges per gather round: lane group
// g = lane>>3 handles edge e+g; each lane LDG.128s its 16B chunk of the fp16
// z row (8 features).  All gather rounds independent -> deep MLP.
// ---------------------------------------------------------------------------
__global__ void pull_norm_kernel(const float* __restrict__ bias,
                                 float* __restrict__ out) {
    const int lane = threadIdx.x & 31;
    const int row  = blockIdx.x * (blockDim.x >> 5) + (threadIdx.x >> 5);
    if (row >= N_NODES) return;

    const int beg = g_off[row];
    const int end = g_off[row + 1];

    const int j = lane & 7;     // feature-chunk index: features [8j, 8j+8)
    const int g = lane >> 3;    // edge subgroup 0..3

    float2 a0 = make_float2(0.f, 0.f);
    float2 a1 = make_float2(0.f, 0.f);
    float2 a2 = make_float2(0.f, 0.f);
    float2 a3 = make_float2(0.f, 0.f);

    int base = beg;
    int rem  = end - beg;
    while (rem > 0) {
        const int cnt = (rem < 32) ? rem : 32;
        const int2 ed = g_es[base + ((lane < cnt) ? lane : (cnt - 1))];

        for (int e = 0; e < cnt; e += 8) {
            // two independent 4-edge gather rounds per iteration
#pragma unroll
            for (int h = 0; h < 2; h++) {
                const int eidx = e + 4 * h + g;
                const int src  = (eidx < cnt) ? eidx : (cnt - 1);
                const int col  = __shfl_sync(0xffffffffu, ed.x, src);
                float v = __int_as_float(__shfl_sync(0xffffffffu, ed.y, src));
                if (eidx >= cnt) v = 0.f;

                const uint4 zz = *reinterpret_cast<const uint4*>(
                    reinterpret_cast<const char*>(g_z) + (size_t)col * 128 + j * 16);
                const float2 z0 = __half22float2(*reinterpret_cast<const __half2*>(&zz.x));
                const float2 z1 = __half22float2(*reinterpret_cast<const __half2*>(&zz.y));
                const float2 z2 = __half22float2(*reinterpret_cast<const __half2*>(&zz.z));
                const float2 z3 = __half22float2(*reinterpret_cast<const __half2*>(&zz.w));
                a0.x += v * z0.x;  a0.y += v * z0.y;
                a1.x += v * z1.x;  a1.y += v * z1.y;
                a2.x += v * z2.x;  a2.y += v * z2.y;
                a3.x += v * z3.x;  a3.y += v * z3.y;
            }
        }
        base += cnt;
        rem  -= cnt;
    }

    // ---- reduce across the 4 edge subgroups (xor keeps all lanes valid) ----
#pragma unroll
    for (int o = 8; o <= 16; o <<= 1) {
        a0.x += __shfl_xor_sync(0xffffffffu, a0.x, o);
        a0.y += __shfl_xor_sync(0xffffffffu, a0.y, o);
        a1.x += __shfl_xor_sync(0xffffffffu, a1.x, o);
        a1.y += __shfl_xor_sync(0xffffffffu, a1.y, o);
        a2.x += __shfl_xor_sync(0xffffffffu, a2.x, o);
        a2.y += __shfl_xor_sync(0xffffffffu, a2.y, o);
        a3.x += __shfl_xor_sync(0xffffffffu, a3.x, o);
        a3.y += __shfl_xor_sync(0xffffffffu, a3.y, o);
    }

    // ---- bias ----
    const float2* b2 = reinterpret_cast<const float2*>(bias);
    const float2 bb0 = b2[j * 4 + 0];
    const float2 bb1 = b2[j * 4 + 1];
    const float2 bb2 = b2[j * 4 + 2];
    const float2 bb3 = b2[j * 4 + 3];
    a0.x += bb0.x; a0.y += bb0.y;
    a1.x += bb1.x; a1.y += bb1.y;
    a2.x += bb2.x; a2.y += bb2.y;
    a3.x += bb3.x; a3.y += bb3.y;

    // ---- row L2 norm: per-lane sq over 8 features, reduce within 8 lanes ----
    float sq = a0.x * a0.x + a0.y * a0.y + a1.x * a1.x + a1.y * a1.y
             + a2.x * a2.x + a2.y * a2.y + a3.x * a3.x + a3.y * a3.y;
#pragma unroll
    for (int o = 1; o <= 4; o <<= 1)
        sq += __shfl_xor_sync(0xffffffffu, sq, o);
    const float inv = rsqrtf(sq);

    // ---- store: lanes 0..7 (group 0) write 8 floats each ----
    if (g == 0) {
        float4* o4 = reinterpret_cast<float4*>(out + (size_t)row * F + j * 8);
        o4[0] = make_float4(a0.x * inv, a0.y * inv, a1.x * inv, a1.y * inv);
        o4[1] = make_float4(a2.x * inv, a2.y * inv, a3.x * inv, a3.y * inv);
    }
}

// ---------------------------------------------------------------------------
// Launch
// inputs: x, edge_row, edge_col, edge_val, weight, bias
// ---------------------------------------------------------------------------
extern "C" void kernel_launch(void* const* d_in, const int* in_sizes, int n_in,
                              void* d_out, int out_size) {
    const float* x        = (const float*)d_in[0];
    const int*   edge_row = (const int*)  d_in[1];
    const int*   edge_col = (const int*)  d_in[2];
    const float* edge_val = (const float*)d_in[3];
    const float* weight   = (const float*)d_in[4];
    const float* bias     = (const float*)d_in[5];
    float*       out      = (float*)d_out;

    const int n_edges = in_sizes[1];

    const int rows_per_block = 256 / 32;
    const int nblocks = (N_NODES + rows_per_block - 1) / rows_per_block;

    zero_deg_kernel<<<98, 1024>>>();
    hist_kernel<<<1184, 256>>>(edge_row, n_edges);
    scan_local_kernel<<<NSCAN, SCAN_BLK>>>();
    scan_add_kernel<<<NSCAN, SCAN_BLK>>>();
    bucket_kernel<<<1184, 256>>>(edge_row, edge_col, edge_val, n_edges);
    zgemm_kernel<<<nblocks, 256>>>(x, weight);
    pull_norm_kernel<<<nblocks, 256>>>(bias, out);
}